// round 10
// baseline (speedup 1.0000x reference)
#include <cuda_runtime.h>
#include <cuda_fp16.h>

#define BB 128
#define LL 512
#define KN 8
#define DD 300
#define CC 14
#define LCHUNK 64
#define NCHUNK (LL / LCHUNK)   // 8
#define NPOS (BB * LL)         // 65536 positions
#define NROWS 4905             // NUM_NODES + 1
#define RSTRIDE 320            // halves per row: 640B = 5 x 128B sectors
#define RH2 (RSTRIDE / 2)      // 160 half2 per row
#define CVT_WARPS 16
#define CVT_BLKS ((NROWS + CVT_WARPS - 1) / CVT_WARPS)   // 307
#define SMETA_BLKS 256          // slave/edge metadata: 256 blks x 512 thr x 4
#define MMETA_BLKS 32           // master/gate metadata: 32 blks x 512 thr x 4

// fp16 copy of R, row-padded for sector alignment
__device__ __half2 g_Rh2[NROWS * RH2];
// Deterministic partial-sum scratch: [chunk][b][d]
__device__ float g_part[NCHUNK * BB * DD];
// Precomputed metadata
__device__ __align__(16) int   g_node[NPOS * KN];   // slave idx pre-scaled
__device__ __align__(16) float g_e[NPOS * KN];      // E[edge]
__device__ __align__(16) int   g_m[NPOS];           // master idx pre-scaled
__device__ __align__(16) float g_g[NPOS];           // Ngate[master]
// Per-batch completion counters (reset by prep every replay)
__device__ unsigned int g_counter[BB];

__device__ __forceinline__ unsigned int atomAddRelease(unsigned int* p, unsigned int v)
{
    unsigned int old;
    asm volatile("atom.release.gpu.global.add.u32 %0, [%1], %2;"
                 : "=r"(old) : "l"(p), "r"(v) : "memory");
    return old;
}

__global__ __launch_bounds__(512)
void prep_kernel(const float* __restrict__ R,
                 const int*   __restrict__ master,
                 const int*   __restrict__ slave,
                 const int*   __restrict__ edge,
                 const float* __restrict__ E,
                 const float* __restrict__ Ngate)
{
    const int t = threadIdx.x;

    if (blockIdx.x < CVT_BLKS) {
        // ---- convert role: one warp per R row ----
        if (blockIdx.x == 0 && t < BB)
            g_counter[t] = 0u;   // reset fusion counters each replay

        const int wid  = t >> 5;
        const int lane = t & 31;
        const int row  = blockIdx.x * CVT_WARPS + wid;
        if (row >= NROWS) return;

        const float* src = R + row * DD;
        __half2*     dst = g_Rh2 + row * RH2;

        float2 v[5];
        #pragma unroll
        for (int j = 0; j < 5; ++j) {
            const int tt = lane + j * 32;
            v[j] = (tt < DD / 2) ? *(const float2*)&src[tt * 2]
                                 : make_float2(0.f, 0.f);
        }
        #pragma unroll
        for (int j = 0; j < 5; ++j) {
            const int tt = lane + j * 32;
            if (tt < RH2)
                dst[tt] = __floats2half2_rn(v[j].x, v[j].y);
        }
    } else if (blockIdx.x < CVT_BLKS + SMETA_BLKS) {
        // ---- slave/edge metadata: int4 loads -> 4 independent E gathers ----
        const int gid = (blockIdx.x - CVT_BLKS) * 512 + t;   // 0..131071
        const int4 s4 = ((const int4*)slave)[gid];
        const int4 e4 = ((const int4*)edge)[gid];

        const float v0 = E[e4.x];
        const float v1 = E[e4.y];
        const float v2 = E[e4.z];
        const float v3 = E[e4.w];

        int4 n4;
        n4.x = s4.x * RH2;  n4.y = s4.y * RH2;
        n4.z = s4.z * RH2;  n4.w = s4.w * RH2;

        ((int4*)g_node)[gid] = n4;
        ((float4*)g_e)[gid]  = make_float4(v0, v1, v2, v3);
    } else {
        // ---- master/gate metadata: int4 loads -> 4 independent Ngate gathers ----
        const int gid = (blockIdx.x - CVT_BLKS - SMETA_BLKS) * 512 + t;  // 0..16383
        const int4 m4 = ((const int4*)master)[gid];

        const float g0 = Ngate[m4.x];
        const float g1 = Ngate[m4.y];
        const float g2 = Ngate[m4.z];
        const float g3 = Ngate[m4.w];

        int4 mm;
        mm.x = m4.x * RH2;  mm.y = m4.y * RH2;
        mm.z = m4.z * RH2;  mm.w = m4.w * RH2;

        ((int4*)g_m)[gid] = mm;
        ((float4*)g_g)[gid] = make_float4(g0, g1, g2, g3);
    }
}

__global__ __launch_bounds__(160)
void gnn_pool_kernel(const float* __restrict__ W,
                     const float* __restrict__ bias,
                     float* __restrict__ out)
{
    const int b     = blockIdx.y;
    const int chunk = blockIdx.x;
    const int tid   = threadIdx.x;

    __shared__ __align__(16) int   s_node[LCHUNK * KN];
    __shared__ __align__(16) float s_e[LCHUNK * KN];
    __shared__ int   s_m[LCHUNK];
    __shared__ float s_g[LCHUNK];

    const int base = b * LL + chunk * LCHUNK;

    // Coalesced copy of precomputed metadata
    #pragma unroll
    for (int r = 0; r < 4; ++r) {
        const int i = tid + r * 160;
        if (i < LCHUNK * KN) {
            s_node[i] = g_node[base * KN + i];
            s_e[i]    = g_e[base * KN + i];
        }
    }
    if (tid < LCHUNK) {
        s_m[tid] = g_m[base + tid];
        s_g[tid] = g_g[base + tid];
    }
    __syncthreads();

    const bool active = (tid < 150);   // 150 half2 lanes cover 300 dims

    if (active) {
        const __half2* Rbase = g_Rh2 + tid;
        float2 acc = make_float2(0.f, 0.f);

        #pragma unroll 4
        for (int li = 0; li < LCHUNK; ++li) {
            const int4   n0 = *(const int4*)  &s_node[li * KN];
            const int4   n1 = *(const int4*)  &s_node[li * KN + 4];
            const float4 e0 = *(const float4*)&s_e[li * KN];
            const float4 e1 = *(const float4*)&s_e[li * KN + 4];

            const float2 f0 = __half22float2(Rbase[n0.x]);
            const float2 f1 = __half22float2(Rbase[n0.y]);
            const float2 f2 = __half22float2(Rbase[n0.z]);
            const float2 f3 = __half22float2(Rbase[n0.w]);
            const float2 f4 = __half22float2(Rbase[n1.x]);
            const float2 f5 = __half22float2(Rbase[n1.y]);
            const float2 f6 = __half22float2(Rbase[n1.z]);
            const float2 f7 = __half22float2(Rbase[n1.w]);
            const float2 fm = __half22float2(Rbase[s_m[li]]);

            float mx0 = f0.x * e0.x;
            float mx1 = f0.y * e0.x;
            mx0 = fmaxf(mx0, f1.x * e0.y);  mx1 = fmaxf(mx1, f1.y * e0.y);
            mx0 = fmaxf(mx0, f2.x * e0.z);  mx1 = fmaxf(mx1, f2.y * e0.z);
            mx0 = fmaxf(mx0, f3.x * e0.w);  mx1 = fmaxf(mx1, f3.y * e0.w);
            mx0 = fmaxf(mx0, f4.x * e1.x);  mx1 = fmaxf(mx1, f4.y * e1.x);
            mx0 = fmaxf(mx0, f5.x * e1.y);  mx1 = fmaxf(mx1, f5.y * e1.y);
            mx0 = fmaxf(mx0, f6.x * e1.z);  mx1 = fmaxf(mx1, f6.y * e1.z);
            mx0 = fmaxf(mx0, f7.x * e1.w);  mx1 = fmaxf(mx1, f7.y * e1.w);

            const float g = s_g[li];
            acc.x += mx0 + g * (fm.x - mx0);
            acc.y += mx1 + g * (fm.y - mx1);
        }

        // L1-bypassing write-through to L2 (visible to the last block's __ldcg)
        __stcg((float2*)&g_part[(chunk * BB + b) * DD + tid * 2], acc);
    }

    // ---- fused head: release-atomic handshake, no membar/CCTL ----
    __syncthreads();                       // all partial stores issued
    __shared__ unsigned int s_old;
    if (tid == 0)
        s_old = atomAddRelease(&g_counter[b], 1u);
    __syncthreads();
    if (s_old != NCHUNK - 1) return;       // only the 8th block proceeds

    __shared__ float sx[DD];
    __shared__ float sh[CC];

    // Reduce the 8 partials (L2-direct loads; fixed order -> deterministic)
    if (active) {
        float2 s = make_float2(0.f, 0.f);
        #pragma unroll
        for (int c = 0; c < NCHUNK; ++c) {
            const float2 p = __ldcg((const float2*)&g_part[(c * BB + b) * DD + tid * 2]);
            s.x += p.x;
            s.y += p.y;
        }
        sx[tid * 2]     = s.x;
        sx[tid * 2 + 1] = s.y;
    }
    __syncthreads();

    // FC: 5 warps, warp w handles classes 3w..3w+2 (14 of 15 slots)
    {
        const int wid  = tid >> 5;
        const int lane = tid & 31;
        #pragma unroll
        for (int j = 0; j < 3; ++j) {
            const int c = wid * 3 + j;
            if (c < CC) {
                float s = 0.f;
                #pragma unroll
                for (int it = 0; it < 10; ++it) {
                    const int d = lane + it * 32;
                    if (d < DD) s += sx[d] * W[c * DD + d];
                }
                #pragma unroll
                for (int off = 16; off; off >>= 1)
                    s += __shfl_down_sync(0xffffffffu, s, off);
                if (lane == 0)
                    sh[c] = fmaxf(s + bias[c], 0.f);
            }
        }
    }
    __syncthreads();

    // Parallel softmax over 14 classes (warp 0)
    if (tid < 32) {
        const float h = (tid < CC) ? sh[tid] : -1e30f;
        float m = h;
        #pragma unroll
        for (int off = 16; off; off >>= 1)
            m = fmaxf(m, __shfl_xor_sync(0xffffffffu, m, off));
        const float e = (tid < CC) ? expf(h - m) : 0.f;
        float sum = e;
        #pragma unroll
        for (int off = 16; off; off >>= 1)
            sum += __shfl_xor_sync(0xffffffffu, sum, off);
        if (tid < CC)
            out[b * CC + tid] = e / sum;
    }
}

extern "C" void kernel_launch(void* const* d_in, const int* in_sizes, int n_in,
                              void* d_out, int out_size)
{
    const int*   master = (const int*)  d_in[0];
    const int*   slave  = (const int*)  d_in[1];
    const int*   edge   = (const int*)  d_in[2];
    const float* R      = (const float*)d_in[3];
    const float* E      = (const float*)d_in[4];
    const float* Ngate  = (const float*)d_in[5];
    const float* W      = (const float*)d_in[6];
    const float* bias   = (const float*)d_in[7];
    float* out = (float*)d_out;

    prep_kernel<<<CVT_BLKS + SMETA_BLKS + MMETA_BLKS, 512>>>(R, master, slave,
                                                             edge, E, Ngate);
    gnn_pool_kernel<<<dim3(NCHUNK, BB), 160>>>(W, bias, out);
}

// round 11
// speedup vs baseline: 1.0135x; 1.0135x over previous
#include <cuda_runtime.h>
#include <cuda_fp16.h>

#define BB 128
#define LL 512
#define KN 8
#define DD 300
#define CC 14
#define LCHUNK 64
#define NCHUNK (LL / LCHUNK)   // 8
#define NPOS (BB * LL)         // 65536 positions
#define NROWS 4905             // NUM_NODES + 1
#define RSTRIDE 320            // halves per row: 640B = 5 x 128B sectors
#define RH2 (RSTRIDE / 2)      // 160 half2 per row
#define CVT_WARPS 16
#define CVT_BLKS ((NROWS + CVT_WARPS - 1) / CVT_WARPS)   // 307
#define SMETA_BLKS 256          // slave/edge metadata: 256 blks x 512 thr x 4
#define MMETA_BLKS 32           // master/gate metadata: 32 blks x 512 thr x 4

// fp16 copy of R, row-padded for sector alignment
__device__ __half2 g_Rh2[NROWS * RH2];
// Deterministic partial-sum scratch: [chunk][b][d]
__device__ float g_part[NCHUNK * BB * DD];
// Precomputed metadata (written by prep, read coalesced by pool)
__device__ __align__(16) int   g_node[NPOS * KN];   // slave idx pre-scaled
__device__ __align__(16) float g_e[NPOS * KN];      // E[edge]
__device__ __align__(16) int   g_m[NPOS];           // master idx pre-scaled
__device__ __align__(16) float g_g[NPOS];           // Ngate[master]

__global__ __launch_bounds__(512)
void prep_kernel(const float* __restrict__ R,
                 const int*   __restrict__ master,
                 const int*   __restrict__ slave,
                 const int*   __restrict__ edge,
                 const float* __restrict__ E,
                 const float* __restrict__ Ngate)
{
    const int t = threadIdx.x;

    if (blockIdx.x < CVT_BLKS) {
        // ---- convert role: one warp per R row, MLP=5 ----
        const int wid  = t >> 5;
        const int lane = t & 31;
        const int row  = blockIdx.x * CVT_WARPS + wid;
        if (row >= NROWS) return;

        const float* src = R + row * DD;
        __half2*     dst = g_Rh2 + row * RH2;

        float2 v[5];
        #pragma unroll
        for (int j = 0; j < 5; ++j) {
            const int tt = lane + j * 32;
            v[j] = (tt < DD / 2) ? *(const float2*)&src[tt * 2]
                                 : make_float2(0.f, 0.f);
        }
        #pragma unroll
        for (int j = 0; j < 5; ++j) {
            const int tt = lane + j * 32;
            if (tt < RH2)
                dst[tt] = __floats2half2_rn(v[j].x, v[j].y);
        }
    } else if (blockIdx.x < CVT_BLKS + SMETA_BLKS) {
        // ---- slave/edge metadata: int4 loads -> 4 independent E gathers ----
        const int gid = (blockIdx.x - CVT_BLKS) * 512 + t;   // 0..131071
        const int4 s4 = ((const int4*)slave)[gid];
        const int4 e4 = ((const int4*)edge)[gid];

        const float v0 = E[e4.x];
        const float v1 = E[e4.y];
        const float v2 = E[e4.z];
        const float v3 = E[e4.w];

        int4 n4;
        n4.x = s4.x * RH2;  n4.y = s4.y * RH2;
        n4.z = s4.z * RH2;  n4.w = s4.w * RH2;

        ((int4*)g_node)[gid] = n4;
        ((float4*)g_e)[gid]  = make_float4(v0, v1, v2, v3);
    } else {
        // ---- master/gate metadata: int4 loads -> 4 independent Ngate gathers ----
        const int gid = (blockIdx.x - CVT_BLKS - SMETA_BLKS) * 512 + t;  // 0..16383
        const int4 m4 = ((const int4*)master)[gid];

        const float g0 = Ngate[m4.x];
        const float g1 = Ngate[m4.y];
        const float g2 = Ngate[m4.z];
        const float g3 = Ngate[m4.w];

        int4 mm;
        mm.x = m4.x * RH2;  mm.y = m4.y * RH2;
        mm.z = m4.z * RH2;  mm.w = m4.w * RH2;

        ((int4*)g_m)[gid] = mm;
        ((float4*)g_g)[gid] = make_float4(g0, g1, g2, g3);
    }
}

__global__ __launch_bounds__(160)
void gnn_pool_kernel()
{
    const int b     = blockIdx.y;
    const int chunk = blockIdx.x;
    const int tid   = threadIdx.x;

    __shared__ __align__(16) int   s_node[LCHUNK * KN];
    __shared__ __align__(16) float s_e[LCHUNK * KN];
    __shared__ int   s_m[LCHUNK];
    __shared__ float s_g[LCHUNK];

    const int base = b * LL + chunk * LCHUNK;

    // Coalesced copy of precomputed metadata (no random gathers here)
    #pragma unroll
    for (int r = 0; r < 4; ++r) {
        const int i = tid + r * 160;
        if (i < LCHUNK * KN) {
            s_node[i] = g_node[base * KN + i];
            s_e[i]    = g_e[base * KN + i];
        }
    }
    if (tid < LCHUNK) {
        s_m[tid] = g_m[base + tid];
        s_g[tid] = g_g[base + tid];
    }
    __syncthreads();

    if (tid >= 150) return;   // 150 half2 lanes cover 300 dims

    const __half2* Rbase = g_Rh2 + tid;
    float2 acc = make_float2(0.f, 0.f);

    #pragma unroll 4
    for (int li = 0; li < LCHUNK; ++li) {
        const int4   n0 = *(const int4*)  &s_node[li * KN];
        const int4   n1 = *(const int4*)  &s_node[li * KN + 4];
        const float4 e0 = *(const float4*)&s_e[li * KN];
        const float4 e1 = *(const float4*)&s_e[li * KN + 4];

        const float2 f0 = __half22float2(Rbase[n0.x]);
        const float2 f1 = __half22float2(Rbase[n0.y]);
        const float2 f2 = __half22float2(Rbase[n0.z]);
        const float2 f3 = __half22float2(Rbase[n0.w]);
        const float2 f4 = __half22float2(Rbase[n1.x]);
        const float2 f5 = __half22float2(Rbase[n1.y]);
        const float2 f6 = __half22float2(Rbase[n1.z]);
        const float2 f7 = __half22float2(Rbase[n1.w]);
        const float2 fm = __half22float2(Rbase[s_m[li]]);

        float mx0 = f0.x * e0.x;
        float mx1 = f0.y * e0.x;
        mx0 = fmaxf(mx0, f1.x * e0.y);  mx1 = fmaxf(mx1, f1.y * e0.y);
        mx0 = fmaxf(mx0, f2.x * e0.z);  mx1 = fmaxf(mx1, f2.y * e0.z);
        mx0 = fmaxf(mx0, f3.x * e0.w);  mx1 = fmaxf(mx1, f3.y * e0.w);
        mx0 = fmaxf(mx0, f4.x * e1.x);  mx1 = fmaxf(mx1, f4.y * e1.x);
        mx0 = fmaxf(mx0, f5.x * e1.y);  mx1 = fmaxf(mx1, f5.y * e1.y);
        mx0 = fmaxf(mx0, f6.x * e1.z);  mx1 = fmaxf(mx1, f6.y * e1.z);
        mx0 = fmaxf(mx0, f7.x * e1.w);  mx1 = fmaxf(mx1, f7.y * e1.w);

        const float g = s_g[li];
        acc.x += mx0 + g * (fm.x - mx0);
        acc.y += mx1 + g * (fm.y - mx1);
    }

    float2* outp = (float2*)&g_part[(chunk * BB + b) * DD];
    outp[tid] = acc;
}

__global__ __launch_bounds__(448)
void head_kernel(const float* __restrict__ W,
                 const float* __restrict__ bias,
                 float* __restrict__ out)
{
    const int b    = blockIdx.x;
    const int tid  = threadIdx.x;
    const int wid  = tid >> 5;
    const int lane = tid & 31;

    __shared__ float sx[DD];
    __shared__ float sh[CC];

    // Reduce the 8 partials -> X[b][:]  (150 float2 lanes)
    if (tid < 150) {
        float2 s = make_float2(0.f, 0.f);
        #pragma unroll
        for (int c = 0; c < NCHUNK; ++c) {
            const float2 p = *(const float2*)&g_part[(c * BB + b) * DD + tid * 2];
            s.x += p.x;
            s.y += p.y;
        }
        sx[tid * 2]     = s.x;
        sx[tid * 2 + 1] = s.y;
    }
    __syncthreads();

    // One warp per class: h[c] = relu(X . W[c] + bias[c])
    if (wid < CC) {
        float s = 0.f;
        #pragma unroll
        for (int it = 0; it < 10; ++it) {
            const int d = lane + it * 32;
            if (d < DD) s += sx[d] * W[wid * DD + d];
        }
        #pragma unroll
        for (int off = 16; off; off >>= 1)
            s += __shfl_down_sync(0xffffffffu, s, off);
        if (lane == 0)
            sh[wid] = fmaxf(s + bias[wid], 0.f);
    }
    __syncthreads();

    // Parallel softmax over 14 classes (warp 0)
    if (wid == 0) {
        const float h = (lane < CC) ? sh[lane] : -1e30f;
        float m = h;
        #pragma unroll
        for (int off = 16; off; off >>= 1)
            m = fmaxf(m, __shfl_xor_sync(0xffffffffu, m, off));
        const float e = (lane < CC) ? expf(h - m) : 0.f;
        float sum = e;
        #pragma unroll
        for (int off = 16; off; off >>= 1)
            sum += __shfl_xor_sync(0xffffffffu, sum, off);
        if (lane < CC)
            out[b * CC + lane] = e / sum;
    }
}

extern "C" void kernel_launch(void* const* d_in, const int* in_sizes, int n_in,
                              void* d_out, int out_size)
{
    const int*   master = (const int*)  d_in[0];
    const int*   slave  = (const int*)  d_in[1];
    const int*   edge   = (const int*)  d_in[2];
    const float* R      = (const float*)d_in[3];
    const float* E      = (const float*)d_in[4];
    const float* Ngate  = (const float*)d_in[5];
    const float* W      = (const float*)d_in[6];
    const float* bias   = (const float*)d_in[7];
    float* out = (float*)d_out;

    prep_kernel<<<CVT_BLKS + SMETA_BLKS + MMETA_BLKS, 512>>>(R, master, slave,
                                                             edge, E, Ngate);
    gnn_pool_kernel<<<dim3(NCHUNK, BB), 160>>>();
    head_kernel<<<BB, 448>>>(W, bias, out);
}

// round 12
// speedup vs baseline: 1.0606x; 1.0464x over previous
#include <cuda_runtime.h>
#include <cuda_fp16.h>

#define BB 128
#define LL 512
#define KN 8
#define DD 300
#define CC 14
#define LCHUNK 64
#define NCHUNK (LL / LCHUNK)   // 8
#define NPOS (BB * LL)         // 65536 positions
#define NROWS 4905             // NUM_NODES + 1
#define RSTRIDE 320            // halves per row: 640B = 5 x 128B sectors
#define RH2 (RSTRIDE / 2)      // 160 half2 per row
#define CVT_WARPS 16
#define CVT_BLKS ((NROWS + CVT_WARPS - 1) / CVT_WARPS)   // 307
#define SMETA_BLKS 256
#define MMETA_BLKS 32

__device__ __half2 g_Rh2[NROWS * RH2];
__device__ float g_part[NCHUNK * BB * DD];
__device__ __align__(16) int   g_node[NPOS * KN];
__device__ __align__(16) float g_e[NPOS * KN];
__device__ __align__(16) int   g_m[NPOS];
__device__ __align__(16) float g_g[NPOS];

__device__ __forceinline__ void pdl_wait()
{
    asm volatile("griddepcontrol.wait;" ::: "memory");
}

__global__ __launch_bounds__(512)
void prep_kernel(const float* __restrict__ R,
                 const int*   __restrict__ master,
                 const int*   __restrict__ slave,
                 const int*   __restrict__ edge,
                 const float* __restrict__ E,
                 const float* __restrict__ Ngate)
{
    const int t = threadIdx.x;

    if (blockIdx.x < CVT_BLKS) {
        // ---- convert role: one warp per R row, MLP=5 ----
        const int wid  = t >> 5;
        const int lane = t & 31;
        const int row  = blockIdx.x * CVT_WARPS + wid;
        if (row >= NROWS) return;

        const float* src = R + row * DD;
        __half2*     dst = g_Rh2 + row * RH2;

        float2 v[5];
        #pragma unroll
        for (int j = 0; j < 5; ++j) {
            const int tt = lane + j * 32;
            v[j] = (tt < DD / 2) ? *(const float2*)&src[tt * 2]
                                 : make_float2(0.f, 0.f);
        }
        #pragma unroll
        for (int j = 0; j < 5; ++j) {
            const int tt = lane + j * 32;
            if (tt < RH2)
                dst[tt] = __floats2half2_rn(v[j].x, v[j].y);
        }
    } else if (blockIdx.x < CVT_BLKS + SMETA_BLKS) {
        // ---- slave/edge metadata ----
        const int gid = (blockIdx.x - CVT_BLKS) * 512 + t;
        const int4 s4 = ((const int4*)slave)[gid];
        const int4 e4 = ((const int4*)edge)[gid];

        const float v0 = E[e4.x];
        const float v1 = E[e4.y];
        const float v2 = E[e4.z];
        const float v3 = E[e4.w];

        int4 n4;
        n4.x = s4.x * RH2;  n4.y = s4.y * RH2;
        n4.z = s4.z * RH2;  n4.w = s4.w * RH2;

        ((int4*)g_node)[gid] = n4;
        ((float4*)g_e)[gid]  = make_float4(v0, v1, v2, v3);
    } else {
        // ---- master/gate metadata ----
        const int gid = (blockIdx.x - CVT_BLKS - SMETA_BLKS) * 512 + t;
        const int4 m4 = ((const int4*)master)[gid];

        const float g0 = Ngate[m4.x];
        const float g1 = Ngate[m4.y];
        const float g2 = Ngate[m4.z];
        const float g3 = Ngate[m4.w];

        int4 mm;
        mm.x = m4.x * RH2;  mm.y = m4.y * RH2;
        mm.z = m4.z * RH2;  mm.w = m4.w * RH2;

        ((int4*)g_m)[gid] = mm;
        ((float4*)g_g)[gid] = make_float4(g0, g1, g2, g3);
    }
}

__global__ __launch_bounds__(160)
void gnn_pool_kernel()
{
    const int b     = blockIdx.y;
    const int chunk = blockIdx.x;
    const int tid   = threadIdx.x;

    pdl_wait();   // prep outputs must be complete

    __shared__ __align__(16) int   s_node[LCHUNK * KN];
    __shared__ __align__(16) float s_e[LCHUNK * KN];
    __shared__ int   s_m[LCHUNK];
    __shared__ float s_g[LCHUNK];

    const int base = b * LL + chunk * LCHUNK;

    #pragma unroll
    for (int r = 0; r < 4; ++r) {
        const int i = tid + r * 160;
        if (i < LCHUNK * KN) {
            s_node[i] = g_node[base * KN + i];
            s_e[i]    = g_e[base * KN + i];
        }
    }
    if (tid < LCHUNK) {
        s_m[tid] = g_m[base + tid];
        s_g[tid] = g_g[base + tid];
    }
    __syncthreads();

    if (tid >= 150) return;

    const __half2* Rbase = g_Rh2 + tid;
    float2 acc = make_float2(0.f, 0.f);

    #pragma unroll 4
    for (int li = 0; li < LCHUNK; ++li) {
        const int4   n0 = *(const int4*)  &s_node[li * KN];
        const int4   n1 = *(const int4*)  &s_node[li * KN + 4];
        const float4 e0 = *(const float4*)&s_e[li * KN];
        const float4 e1 = *(const float4*)&s_e[li * KN + 4];

        const float2 f0 = __half22float2(Rbase[n0.x]);
        const float2 f1 = __half22float2(Rbase[n0.y]);
        const float2 f2 = __half22float2(Rbase[n0.z]);
        const float2 f3 = __half22float2(Rbase[n0.w]);
        const float2 f4 = __half22float2(Rbase[n1.x]);
        const float2 f5 = __half22float2(Rbase[n1.y]);
        const float2 f6 = __half22float2(Rbase[n1.z]);
        const float2 f7 = __half22float2(Rbase[n1.w]);
        const float2 fm = __half22float2(Rbase[s_m[li]]);

        float mx0 = f0.x * e0.x;
        float mx1 = f0.y * e0.x;
        mx0 = fmaxf(mx0, f1.x * e0.y);  mx1 = fmaxf(mx1, f1.y * e0.y);
        mx0 = fmaxf(mx0, f2.x * e0.z);  mx1 = fmaxf(mx1, f2.y * e0.z);
        mx0 = fmaxf(mx0, f3.x * e0.w);  mx1 = fmaxf(mx1, f3.y * e0.w);
        mx0 = fmaxf(mx0, f4.x * e1.x);  mx1 = fmaxf(mx1, f4.y * e1.x);
        mx0 = fmaxf(mx0, f5.x * e1.y);  mx1 = fmaxf(mx1, f5.y * e1.y);
        mx0 = fmaxf(mx0, f6.x * e1.z);  mx1 = fmaxf(mx1, f6.y * e1.z);
        mx0 = fmaxf(mx0, f7.x * e1.w);  mx1 = fmaxf(mx1, f7.y * e1.w);

        const float g = s_g[li];
        acc.x += mx0 + g * (fm.x - mx0);
        acc.y += mx1 + g * (fm.y - mx1);
    }

    float2* outp = (float2*)&g_part[(chunk * BB + b) * DD];
    outp[tid] = acc;
}

__global__ __launch_bounds__(448)
void head_kernel(const float* __restrict__ W,
                 const float* __restrict__ bias,
                 float* __restrict__ out)
{
    const int b    = blockIdx.x;
    const int tid  = threadIdx.x;
    const int wid  = tid >> 5;
    const int lane = tid & 31;

    __shared__ float sx[DD];
    __shared__ float sh[CC];

    // ---- pre-wait work: load W + bias (independent of pool) ----
    float wreg[10];
    float bb = 0.f;
    if (wid < CC) {
        #pragma unroll
        for (int it = 0; it < 10; ++it) {
            const int d = lane + it * 32;
            wreg[it] = (d < DD) ? W[wid * DD + d] : 0.f;
        }
        bb = bias[wid];
    }

    pdl_wait();   // g_part must be complete

    // Reduce the 8 partials -> X[b][:]  (150 float2 lanes)
    if (tid < 150) {
        float2 s = make_float2(0.f, 0.f);
        #pragma unroll
        for (int c = 0; c < NCHUNK; ++c) {
            const float2 p = *(const float2*)&g_part[(c * BB + b) * DD + tid * 2];
            s.x += p.x;
            s.y += p.y;
        }
        sx[tid * 2]     = s.x;
        sx[tid * 2 + 1] = s.y;
    }
    __syncthreads();

    // One warp per class, W already in registers
    if (wid < CC) {
        float s = 0.f;
        #pragma unroll
        for (int it = 0; it < 10; ++it) {
            const int d = lane + it * 32;
            if (d < DD) s += sx[d] * wreg[it];
        }
        #pragma unroll
        for (int off = 16; off; off >>= 1)
            s += __shfl_down_sync(0xffffffffu, s, off);
        if (lane == 0)
            sh[wid] = fmaxf(s + bb, 0.f);
    }
    __syncthreads();

    // Parallel softmax over 14 classes (warp 0)
    if (wid == 0) {
        const float h = (lane < CC) ? sh[lane] : -1e30f;
        float m = h;
        #pragma unroll
        for (int off = 16; off; off >>= 1)
            m = fmaxf(m, __shfl_xor_sync(0xffffffffu, m, off));
        const float e = (lane < CC) ? expf(h - m) : 0.f;
        float sum = e;
        #pragma unroll
        for (int off = 16; off; off >>= 1)
            sum += __shfl_xor_sync(0xffffffffu, sum, off);
        if (lane < CC)
            out[b * CC + lane] = e / sum;
    }
}

extern "C" void kernel_launch(void* const* d_in, const int* in_sizes, int n_in,
                              void* d_out, int out_size)
{
    const int*   master = (const int*)  d_in[0];
    const int*   slave  = (const int*)  d_in[1];
    const int*   edge   = (const int*)  d_in[2];
    const float* R      = (const float*)d_in[3];
    const float* E      = (const float*)d_in[4];
    const float* Ngate  = (const float*)d_in[5];
    const float* W      = (const float*)d_in[6];
    const float* bias   = (const float*)d_in[7];
    float* out = (float*)d_out;

    // 1) prep: normal launch
    prep_kernel<<<CVT_BLKS + SMETA_BLKS + MMETA_BLKS, 512>>>(R, master, slave,
                                                             edge, E, Ngate);

    cudaLaunchAttribute attr[1];
    attr[0].id = cudaLaunchAttributeProgrammaticStreamSerialization;
    attr[0].val.programmaticStreamSerializationAllowed = 1;

    // 2) pool: PDL after prep
    {
        cudaLaunchConfig_t cfg = {};
        cfg.gridDim  = dim3(NCHUNK, BB);
        cfg.blockDim = dim3(160);
        cfg.stream   = 0;
        cfg.attrs    = attr;
        cfg.numAttrs = 1;
        cudaLaunchKernelEx(&cfg, gnn_pool_kernel);
    }

    // 3) head: PDL after pool (W preload overlaps pool drain)
    {
        cudaLaunchConfig_t cfg = {};
        cfg.gridDim  = dim3(BB);
        cfg.blockDim = dim3(448);
        cfg.stream   = 0;
        cfg.attrs    = attr;
        cfg.numAttrs = 1;
        cudaLaunchKernelEx(&cfg, head_kernel, W, bias, out);
    }
}